// round 11
// baseline (speedup 1.0000x reference)
#include <cuda_runtime.h>
#include <cuda_bf16.h>

// SimpleLSTM: T=2048, B=1024, I=4, H=10, O=4
// 10 lanes per hidden-state, 3 chains per phase, 2 phases per warp (6 chains/warp).
// Phase interleaving fills SHFL/MUFU latency of one phase with the other's FMAs.

#define TT 2048
#define BB 1024
#define II 4
#define HH 10
#define OO 4
#define PF 4   // x prefetch depth per phase (power of 2)
#define NP 2   // phases (independent chain groups per warp)
#define CPW 3  // chains per phase (lanes 0..29)

__device__ __forceinline__ float tanh_fast(float x) {
    float r;
    asm("tanh.approx.f32 %0, %1;" : "=f"(r) : "f"(x));
    return r;
}
__device__ __forceinline__ float sigmoid_fast(float x) {
    return fmaf(0.5f, tanh_fast(0.5f * x), 0.5f);
}

__global__ void __launch_bounds__(32, 1) lstm_kernel(
    const float* __restrict__ x,
    const float* __restrict__ h0,
    const float* __restrict__ c0,
    const float* __restrict__ W_ih,
    const float* __restrict__ W_hh,
    const float* __restrict__ b_ih,
    const float* __restrict__ b_hh,
    const float* __restrict__ W_fc,
    const float* __restrict__ b_fc,
    float* __restrict__ out,
    int out_size)
{
    const int lane  = threadIdx.x;            // 0..31
    const int group = lane / HH;              // 0..2 valid, 3 = idle lanes 30,31
    const int j     = lane - group * HH;      // hidden unit 0..9
    const bool lane_ok = (lane < CPW * HH);
    const int shfl_base = group * HH;

    // ---- per-lane weights (shared by both phases): rows {j,10+j,20+j,30+j}
    float wih[4][II];
    float whh[4][HH];
    float bias[4];
#pragma unroll
    for (int k = 0; k < 4; k++) {
        const int row = k * HH + j;
        bias[k] = b_ih[row] + b_hh[row];
#pragma unroll
        for (int i = 0; i < II; i++) wih[k][i] = W_ih[row * II + i];
#pragma unroll
        for (int jj = 0; jj < HH; jj++) whh[k][jj] = W_hh[row * HH + jj];
    }
    const int jr = (j < OO) ? j : 0;
    float wfc[HH];
#pragma unroll
    for (int jj = 0; jj < HH; jj++) wfc[jj] = W_fc[jr * HH + jj];
    const float bfc = b_fc[jr];

    // ---- per-phase state
    bool act[NP];
    int  bidx[NP];
    float c[NP], h[NP];
    float h_all[NP][HH];
    const float4* xb[NP];
    float4 xv[NP][PF];
    float* op[NP];

#pragma unroll
    for (int q = 0; q < NP; q++) {
        const int b = blockIdx.x * (CPW * NP) + q * CPW + group;
        act[q] = lane_ok && (b < BB);
        const int bc = act[q] ? b : (BB - 1);
        bidx[q] = bc;
        c[q] = c0[bc * HH + j];
        h[q] = h0[bc * HH + j];
#pragma unroll
        for (int jj = 0; jj < HH; jj++)
            h_all[q][jj] = __shfl_sync(0xffffffffu, h[q], shfl_base + jj);
        xb[q] = reinterpret_cast<const float4*>(x) + bc;
#pragma unroll
        for (int p = 0; p < PF; p++) xv[q][p] = xb[q][p * BB];
        op[q] = out + (size_t)bc * OO + j;
    }

#pragma unroll 2
    for (int t = 0; t < TT; t++) {
        float4 xc[NP];
        float  xa[NP][4];
        float  a[NP][4];

        // stage: consume prefetched x, issue next prefetch
#pragma unroll
        for (int q = 0; q < NP; q++) {
            xc[q] = xv[q][t & (PF - 1)];
            int tn = t + PF;
            tn = (tn < TT) ? tn : (TT - 1);
            xv[q][t & (PF - 1)] = xb[q][tn * BB];
        }

        // stage: x-part of gates (independent of h)
#pragma unroll
        for (int q = 0; q < NP; q++) {
#pragma unroll
            for (int k = 0; k < 4; k++) {
                float s0 = fmaf(wih[k][0], xc[q].x, bias[k]);
                float s1 = wih[k][1] * xc[q].y;
                s0 = fmaf(wih[k][2], xc[q].z, s0);
                s1 = fmaf(wih[k][3], xc[q].w, s1);
                xa[q][k] = s0 + s1;
            }
        }

        // stage: h-dot (both phases interleaved, 2 accumulators per gate)
#pragma unroll
        for (int q = 0; q < NP; q++) {
#pragma unroll
            for (int k = 0; k < 4; k++) {
                float s0 = xa[q][k];
                float s1 = 0.0f;
#pragma unroll
                for (int jj = 0; jj < HH; jj += 2) {
                    s0 = fmaf(whh[k][jj],     h_all[q][jj],     s0);
                    s1 = fmaf(whh[k][jj + 1], h_all[q][jj + 1], s1);
                }
                a[q][k] = s0 + s1;
            }
        }

        // stage: activations + state update (MUFUs of both phases pipeline)
#pragma unroll
        for (int q = 0; q < NP; q++) {
            const float ig = sigmoid_fast(a[q][0]);
            const float fg = sigmoid_fast(a[q][1]);
            const float gg = tanh_fast(a[q][2]);
            const float og = sigmoid_fast(a[q][3]);
            c[q] = fmaf(fg, c[q], ig * gg);
            h[q] = og * tanh_fast(c[q]);
        }

        // stage: broadcast new h
#pragma unroll
        for (int q = 0; q < NP; q++) {
#pragma unroll
            for (int jj = 0; jj < HH; jj++)
                h_all[q][jj] = __shfl_sync(0xffffffffu, h[q], shfl_base + jj);
        }

        // stage: fused fc projection + store (lanes j<O emit out[t,b,:])
#pragma unroll
        for (int q = 0; q < NP; q++) {
            float v0 = bfc, v1 = 0.0f;
#pragma unroll
            for (int jj = 0; jj < HH; jj += 2) {
                v0 = fmaf(wfc[jj],     h_all[q][jj],     v0);
                v1 = fmaf(wfc[jj + 1], h_all[q][jj + 1], v1);
            }
            if (act[q] && j < OO) *op[q] = v0 + v1;
            op[q] += BB * OO;
        }
    }

    // final (hT, cT) tails, if the output buffer includes them
    const int main_sz = TT * BB * OO;
    if (out_size >= main_sz + 2 * BB * HH) {
#pragma unroll
        for (int q = 0; q < NP; q++) {
            if (act[q]) {
                out[main_sz + bidx[q] * HH + j]           = h[q];
                out[main_sz + BB * HH + bidx[q] * HH + j] = c[q];
            }
        }
    }
}

extern "C" void kernel_launch(void* const* d_in, const int* in_sizes, int n_in,
                              void* d_out, int out_size)
{
    const float* x    = (const float*)d_in[0];
    const float* h0   = (const float*)d_in[1];
    const float* c0   = (const float*)d_in[2];
    const float* W_ih = (const float*)d_in[3];
    const float* W_hh = (const float*)d_in[4];
    const float* b_ih = (const float*)d_in[5];
    const float* b_hh = (const float*)d_in[6];
    const float* W_fc = (const float*)d_in[7];
    const float* b_fc = (const float*)d_in[8];
    float* out = (float*)d_out;

    const int chains_per_block = CPW * NP;  // 6
    const int nblocks = (BB + chains_per_block - 1) / chains_per_block;  // 171
    lstm_kernel<<<nblocks, 32>>>(x, h0, c0, W_ih, W_hh, b_ih, b_hh,
                                 W_fc, b_fc, out, out_size);
}

// round 13
// speedup vs baseline: 1.3033x; 1.3033x over previous
#include <cuda_runtime.h>
#include <cuda_bf16.h>

// SimpleLSTM: T=2048, B=1024, I=4, H=10, O=4
// 10 lanes per hidden-state, 3 chains per phase, 2 phases per warp (6 chains/warp).
// Phase interleaving fills SHFL/MUFU latency of one phase with the other's FMAs.
// R11 fix: PF=2 with an explicit 2-step loop body (template<int P>) so every
// prefetch-buffer index is a compile-time literal -> no local-memory demotion.

#define TT 2048
#define BB 1024
#define II 4
#define HH 10
#define OO 4
#define NP 2   // phases (independent chain groups per warp)
#define CPW 3  // chains per phase (lanes 0..29)

__device__ __forceinline__ float tanh_fast(float x) {
    float r;
    asm("tanh.approx.f32 %0, %1;" : "=f"(r) : "f"(x));
    return r;
}
__device__ __forceinline__ float sigmoid_fast(float x) {
    return fmaf(0.5f, tanh_fast(0.5f * x), 0.5f);
}

struct PhaseState {
    float c[NP];
    float h[NP];
    float h_all[NP][HH];
    float4 xv[NP][2];        // PF=2 double buffer; indexed only by literal P
    const float4* xb[NP];
    float* op[NP];
    bool act[NP];
};

struct Weights {
    float wih[4][II];
    float whh[4][HH];
    float bias[4];
    float wfc[HH];
    float bfc;
};

// One timestep for both phases, stage-interleaved. P in {0,1} selects the
// x double-buffer slot (compile-time constant).
template <int P>
__device__ __forceinline__ void lstm_step(
    PhaseState& st, const Weights& w, int t, int shfl_base, bool store_pred)
{
    float4 xc[NP];
    float  xa[NP][4];
    float  a[NP][4];

    // consume prefetched x; prefetch t+2 into the same slot (clamped)
#pragma unroll
    for (int q = 0; q < NP; q++) {
        xc[q] = st.xv[q][P];
        int tn = t + 2;
        tn = (tn < TT) ? tn : (TT - 1);
        st.xv[q][P] = st.xb[q][tn * BB];
    }

    // x-part of gates (independent of h)
#pragma unroll
    for (int q = 0; q < NP; q++) {
#pragma unroll
        for (int k = 0; k < 4; k++) {
            float s0 = fmaf(w.wih[k][0], xc[q].x, w.bias[k]);
            float s1 = w.wih[k][1] * xc[q].y;
            s0 = fmaf(w.wih[k][2], xc[q].z, s0);
            s1 = fmaf(w.wih[k][3], xc[q].w, s1);
            xa[q][k] = s0 + s1;
        }
    }

    // h-dot: 10-term per gate, 2 accumulators, phases interleaved
#pragma unroll
    for (int q = 0; q < NP; q++) {
#pragma unroll
        for (int k = 0; k < 4; k++) {
            float s0 = xa[q][k];
            float s1 = 0.0f;
#pragma unroll
            for (int jj = 0; jj < HH; jj += 2) {
                s0 = fmaf(w.whh[k][jj],     st.h_all[q][jj],     s0);
                s1 = fmaf(w.whh[k][jj + 1], st.h_all[q][jj + 1], s1);
            }
            a[q][k] = s0 + s1;
        }
    }

    // activations + state update (both phases' MUFUs pipeline)
#pragma unroll
    for (int q = 0; q < NP; q++) {
        const float ig = sigmoid_fast(a[q][0]);
        const float fg = sigmoid_fast(a[q][1]);
        const float gg = tanh_fast(a[q][2]);
        const float og = sigmoid_fast(a[q][3]);
        st.c[q] = fmaf(fg, st.c[q], ig * gg);
        st.h[q] = og * tanh_fast(st.c[q]);
    }

    // broadcast new h across the chain's 10 lanes
#pragma unroll
    for (int q = 0; q < NP; q++) {
#pragma unroll
        for (int jj = 0; jj < HH; jj++)
            st.h_all[q][jj] = __shfl_sync(0xffffffffu, st.h[q], shfl_base + jj);
    }

    // fused fc projection + store (lanes j<O emit out[t,b,:])
#pragma unroll
    for (int q = 0; q < NP; q++) {
        float v0 = w.bfc, v1 = 0.0f;
#pragma unroll
        for (int jj = 0; jj < HH; jj += 2) {
            v0 = fmaf(w.wfc[jj],     st.h_all[q][jj],     v0);
            v1 = fmaf(w.wfc[jj + 1], st.h_all[q][jj + 1], v1);
        }
        if (st.act[q] && store_pred) *st.op[q] = v0 + v1;
        st.op[q] += BB * OO;
    }
}

__global__ void __launch_bounds__(32, 1) lstm_kernel(
    const float* __restrict__ x,
    const float* __restrict__ h0,
    const float* __restrict__ c0,
    const float* __restrict__ W_ih,
    const float* __restrict__ W_hh,
    const float* __restrict__ b_ih,
    const float* __restrict__ b_hh,
    const float* __restrict__ W_fc,
    const float* __restrict__ b_fc,
    float* __restrict__ out,
    int out_size)
{
    const int lane  = threadIdx.x;            // 0..31
    const int group = lane / HH;              // 0..2 valid, 3 = idle lanes 30,31
    const int j     = lane - group * HH;      // hidden unit 0..9
    const bool lane_ok = (lane < CPW * HH);
    const int shfl_base = group * HH;

    Weights w;
#pragma unroll
    for (int k = 0; k < 4; k++) {
        const int row = k * HH + j;
        w.bias[k] = b_ih[row] + b_hh[row];
#pragma unroll
        for (int i = 0; i < II; i++) w.wih[k][i] = W_ih[row * II + i];
#pragma unroll
        for (int jj = 0; jj < HH; jj++) w.whh[k][jj] = W_hh[row * HH + jj];
    }
    const int jr = (j < OO) ? j : 0;
#pragma unroll
    for (int jj = 0; jj < HH; jj++) w.wfc[jj] = W_fc[jr * HH + jj];
    w.bfc = b_fc[jr];

    PhaseState st;
    int bidx[NP];
#pragma unroll
    for (int q = 0; q < NP; q++) {
        const int b = blockIdx.x * (CPW * NP) + q * CPW + group;
        st.act[q] = lane_ok && (b < BB);
        const int bc = st.act[q] ? b : (BB - 1);
        bidx[q] = bc;
        st.c[q] = c0[bc * HH + j];
        st.h[q] = h0[bc * HH + j];
#pragma unroll
        for (int jj = 0; jj < HH; jj++)
            st.h_all[q][jj] = __shfl_sync(0xffffffffu, st.h[q], shfl_base + jj);
        st.xb[q] = reinterpret_cast<const float4*>(x) + bc;
        st.xv[q][0] = st.xb[q][0];
        st.xv[q][1] = st.xb[q][BB];
        st.op[q] = out + (size_t)bc * OO + j;
    }

    const bool store_pred = (j < OO);
    for (int t = 0; t < TT; t += 2) {
        lstm_step<0>(st, w, t,     shfl_base, store_pred);
        lstm_step<1>(st, w, t + 1, shfl_base, store_pred);
    }

    // final (hT, cT) tails, if the output buffer includes them
    const int main_sz = TT * BB * OO;
    if (out_size >= main_sz + 2 * BB * HH) {
#pragma unroll
        for (int q = 0; q < NP; q++) {
            if (st.act[q]) {
                out[main_sz + bidx[q] * HH + j]           = st.h[q];
                out[main_sz + BB * HH + bidx[q] * HH + j] = st.c[q];
            }
        }
    }
}

extern "C" void kernel_launch(void* const* d_in, const int* in_sizes, int n_in,
                              void* d_out, int out_size)
{
    const float* x    = (const float*)d_in[0];
    const float* h0   = (const float*)d_in[1];
    const float* c0   = (const float*)d_in[2];
    const float* W_ih = (const float*)d_in[3];
    const float* W_hh = (const float*)d_in[4];
    const float* b_ih = (const float*)d_in[5];
    const float* b_hh = (const float*)d_in[6];
    const float* W_fc = (const float*)d_in[7];
    const float* b_fc = (const float*)d_in[8];
    float* out = (float*)d_out;

    const int chains_per_block = CPW * NP;  // 6
    const int nblocks = (BB + chains_per_block - 1) / chains_per_block;  // 171
    lstm_kernel<<<nblocks, 32>>>(x, h0, c0, W_ih, W_hh, b_ih, b_hh,
                                 W_fc, b_fc, out, out_size);
}